// round 4
// baseline (speedup 1.0000x reference)
#include <cuda_runtime.h>
#include <cstdint>
#include <cmath>

#define T_STEPS 4096
#define HH      1024
#define G4      4096          // 4*H gate rows
#define NCTA    128
#define UPC     8             // hidden units per CTA (1024/128)
#define IND     64
#define OUTD    64
#define PACCW   136           // padded pacc row stride (floats) — bank-conflict-free

// ---------------- scratch (static __device__ — no allocation allowed) -------
__device__ float g_Wc0[G4 * IND];              // W_ih0 @ W_in   (4096 x 64)
__device__ float g_bc0[G4];                    // W_ih0@b_in + b_ih0 + b_hh0
__device__ float g_pre0[(size_t)T_STEPS * G4]; // 64 MB
__device__ float g_pre1[(size_t)T_STEPS * G4]; // 64 MB
__device__ float g_H0[(size_t)T_STEPS * HH];   // 16 MB
__device__ float g_H1[(size_t)T_STEPS * HH];   // 16 MB
// tagged h exchange buffers: [parity][cta][8] + tag [parity][cta], per chain
__device__ float g_hbA[2 * NCTA * UPC];
__device__ float g_hbB[2 * NCTA * UPC];
__device__ int   g_tgA[2 * NCTA];
__device__ int   g_tgB[2 * NCTA];

// ---------------- init: zero exchange buffers + tags ------------------------
__global__ void k_init() {
    int i = threadIdx.x;
    #pragma unroll
    for (int j = i; j < 2 * NCTA * UPC; j += 1024) { g_hbA[j] = 0.f; g_hbB[j] = 0.f; }
    if (i < 2 * NCTA) { g_tgA[i] = 0; g_tgB[i] = 0; }
}

// ---------------- Wc0 = W_ih0 @ W_in  (4096x1024 @ 1024x64 -> 4096x64) ------
__global__ __launch_bounds__(256) void k_wc0(const float* __restrict__ Wih0,
                                             const float* __restrict__ Win) {
    int tid = threadIdx.x;
    int tx = tid & 63;
    int ty = tid >> 6;
    int r = blockIdx.x * 4 + ty;
    const float* wr = Wih0 + (size_t)r * HH;
    float acc = 0.f;
    for (int k = 0; k < HH; ++k)
        acc = fmaf(__ldg(&wr[k]), __ldg(&Win[k * IND + tx]), acc);
    g_Wc0[r * IND + tx] = acc;
}

// ---------------- bc0 = W_ih0 @ b_in + b_ih0 + b_hh0 ------------------------
__global__ __launch_bounds__(256) void k_bc0(const float* __restrict__ Wih0,
                                             const float* __restrict__ b_in,
                                             const float* __restrict__ b_ih0,
                                             const float* __restrict__ b_hh0) {
    int r = blockIdx.x * 256 + threadIdx.x;
    const float* wr = Wih0 + (size_t)r * HH;
    float acc = 0.f;
    for (int k = 0; k < HH; ++k)
        acc = fmaf(wr[k], __ldg(&b_in[k]), acc);
    g_bc0[r] = acc + b_ih0[r] + b_hh0[r];
}

// ---------------- pre0 = x @ Wc0^T + bc0   (M=4096, N=4096, K=64) -----------
__global__ __launch_bounds__(256) void k_pre0(const float* __restrict__ inp) {
    __shared__ float Xs[64][IND];
    __shared__ float Ws[64][IND];
    int tid = threadIdx.x;
    int t0 = blockIdx.y * 64;
    int r0 = blockIdx.x * 64;

    #pragma unroll
    for (int i = 0; i < 16; ++i) {
        int idx = tid + i * 256;
        int tr = idx >> 6, d = idx & 63;
        int t = t0 + tr;
        int s = t & 31, st = t >> 5;
        Xs[tr][d] = inp[((size_t)s * 128 + st) * 64 + d];
        Ws[tr][d] = g_Wc0[(r0 + tr) * IND + d];
    }
    __syncthreads();

    int tx = tid & 15, ty = tid >> 4;
    float acc[4][4] = {};
    for (int d = 0; d < 64; ++d) {
        float a[4], b[4];
        #pragma unroll
        for (int i = 0; i < 4; ++i) a[i] = Xs[ty * 4 + i][d];
        #pragma unroll
        for (int j = 0; j < 4; ++j) b[j] = Ws[tx * 4 + j][d];
        #pragma unroll
        for (int i = 0; i < 4; ++i)
            #pragma unroll
            for (int j = 0; j < 4; ++j)
                acc[i][j] = fmaf(a[i], b[j], acc[i][j]);
    }
    #pragma unroll
    for (int i = 0; i < 4; ++i) {
        int t = t0 + ty * 4 + i;
        #pragma unroll
        for (int j = 0; j < 4; ++j) {
            int r = r0 + tx * 4 + j;
            g_pre0[(size_t)t * G4 + r] = acc[i][j] + g_bc0[r];
        }
    }
}

// ---------------- fast activations ------------------------------------------
__device__ __forceinline__ float sigf(float x) {
    return __fdividef(1.f, 1.f + __expf(-x));
}
__device__ __forceinline__ float tanh_fast(float x) {
    float e = __expf(2.f * x);
    return 1.f - __fdividef(2.f, e + 1.f);
}

// ---------------- persistent LSTM chain (tagged-slice exchange) --------------
// 128 CTAs x 1024 threads, grid-resident (1 CTA/SM).
// Matvec: warp w: unit ul=w>>2, quarter q=w&3; lane l covers k=[q*256+l*8,+8)
//   for all 4 gates of unit ul. The 8 h-values lane l needs are exactly the
//   slice produced by CTA (q*32+l): poll its tag (acquire), load 32B, FFMA2.
// Reduce+cell: warp u<8 owns unit u; writes h slice + Hout; tid0 fences+tags.
// Two __syncthreads per step; no global barrier, no atomics.
__global__ __launch_bounds__(1024, 1) void k_chain(const float* __restrict__ Whh,
                                                   const float* __restrict__ pre,
                                                   float* __restrict__ Hout,
                                                   float* __restrict__ hb,
                                                   int* __restrict__ tg) {
    int tid = threadIdx.x;
    int w = tid >> 5, l = tid & 31;
    int b = blockIdx.x;
    int ubase = b * UPC;
    int ul = w >> 2;          // local unit 0..7
    int q  = w & 3;           // k-quarter 0..3
    int unit = ubase + ul;
    int koff = q * 256 + l * 8;
    int src_cta = q * 32 + l; // producer CTA of this lane's h slice

    __shared__ float pacc[32 * PACCW];

    // resident packed weights: gate g, k = koff + 2j{,+1}
    unsigned long long wp[4][4];
    #pragma unroll
    for (int g = 0; g < 4; ++g) {
        const float* wr = Whh + (size_t)(g * HH + unit) * HH + koff;
        ulonglong2 v0 = *reinterpret_cast<const ulonglong2*>(wr);
        ulonglong2 v1 = *reinterpret_cast<const ulonglong2*>(wr + 4);
        wp[g][0] = v0.x; wp[g][1] = v0.y; wp[g][2] = v1.x; wp[g][3] = v1.y;
    }

    // reduce/cell role constants (warps 0..7)
    int rg = l >> 3;                 // gate 0..3
    int rj = l & 7;                  // segment 0..7
    int grow = rg * HH + ubase + w;  // gate row for reduce warp w
    float preg = 0.f;
    if (w < UPC && rj == 0) preg = __ldg(&pre[grow]);   // pre[t=0]
    float c = 0.f;                   // cell state: warp u lane 0

    const int* tag_rd = tg + src_cta;          // + parity*NCTA
    __syncthreads();

    for (int t = 0; t < T_STEPS; ++t) {
        int pr = (t + 1) & 1;       // parity holding h(t-1)
        int pw = t & 1;             // parity to write h(t)

        // --- per-lane: poll producer tag, load slice, matvec ----------------
        {
            const int* tp = tag_rd + pr * NCTA;
            int v;
            do {
                asm volatile("ld.acquire.gpu.global.s32 %0, [%1];"
                             : "=r"(v) : "l"(tp) : "memory");
            } while (v < t);        // writer of h(t-1) set tag = t
        }
        const float4* hp = reinterpret_cast<const float4*>(
            hb + ((size_t)pr * NCTA + src_cta) * UPC);
        float4 h0 = __ldcg(hp);
        float4 h1 = __ldcg(hp + 1);
        unsigned long long hu0, hu1, hu2, hu3;
        asm("mov.b64 %0, {%1, %2};" : "=l"(hu0) : "f"(h0.x), "f"(h0.y));
        asm("mov.b64 %0, {%1, %2};" : "=l"(hu1) : "f"(h0.z), "f"(h0.w));
        asm("mov.b64 %0, {%1, %2};" : "=l"(hu2) : "f"(h1.x), "f"(h1.y));
        asm("mov.b64 %0, {%1, %2};" : "=l"(hu3) : "f"(h1.z), "f"(h1.w));

        unsigned long long acc[4] = {0ull, 0ull, 0ull, 0ull};
        #pragma unroll
        for (int g = 0; g < 4; ++g) {
            asm("fma.rn.f32x2 %0, %1, %2, %0;" : "+l"(acc[g]) : "l"(wp[g][0]), "l"(hu0));
            asm("fma.rn.f32x2 %0, %1, %2, %0;" : "+l"(acc[g]) : "l"(wp[g][1]), "l"(hu1));
            asm("fma.rn.f32x2 %0, %1, %2, %0;" : "+l"(acc[g]) : "l"(wp[g][2]), "l"(hu2));
            asm("fma.rn.f32x2 %0, %1, %2, %0;" : "+l"(acc[g]) : "l"(wp[g][3]), "l"(hu3));
        }
        #pragma unroll
        for (int g = 0; g < 4; ++g) {
            float lo, hi;
            asm("mov.b64 {%0, %1}, %2;" : "=f"(lo), "=f"(hi) : "l"(acc[g]));
            pacc[(ul * 4 + g) * PACCW + q * 32 + l] = lo + hi;
        }
        __syncthreads();                                 // BAR1: pacc ready

        // --- fused reduce + cell: warp u (<8) owns unit u -------------------
        if (w < UPC) {
            int prow = (w * 4 + rg) * PACCW;
            float s = 0.f;
            #pragma unroll
            for (int i = 0; i < 16; ++i)
                s += pacc[prow + 8 * i + rj];
            s += __shfl_xor_sync(0xffffffffu, s, 4);
            s += __shfl_xor_sync(0xffffffffu, s, 2);
            s += __shfl_xor_sync(0xffffffffu, s, 1);
            if (rj == 0) {
                s += preg;
                if (t + 1 < T_STEPS)                      // prefetch pre[t+1]
                    preg = __ldcg(&pre[(size_t)(t + 1) * G4 + grow]);
            }
            float gi = __shfl_sync(0xffffffffu, s, 0);
            float gf = __shfl_sync(0xffffffffu, s, 8);
            float gg = __shfl_sync(0xffffffffu, s, 16);
            float go = __shfl_sync(0xffffffffu, s, 24);
            if (l == 0) {
                float cn = sigf(gf) * c + sigf(gi) * tanh_fast(gg);
                c = cn;
                float h = sigf(go) * tanh_fast(cn);
                hb[((size_t)pw * NCTA + b) * UPC + w] = h;        // exchange slice
                __stcg(&Hout[(size_t)t * HH + ubase + w], h);     // history
            }
        }
        __syncthreads();                                 // BAR2: slice stored

        // --- publish: fence + tag (tid 0 only); consumers poll, no barrier --
        if (tid == 0) {
            __threadfence();
            asm volatile("st.relaxed.gpu.global.s32 [%0], %1;"
                         :: "l"(tg + pw * NCTA + b), "r"(t + 1) : "memory");
        }
    }
}

// ---------------- pre1 = H0 @ W_ih1^T + (b_ih1 + b_hh1) ---------------------
__global__ __launch_bounds__(256) void k_pre1(const float* __restrict__ A,
                                              const float* __restrict__ B,
                                              const float* __restrict__ b1a,
                                              const float* __restrict__ b1b) {
    __shared__ float As[2][8][132];
    __shared__ float Bs[2][8][132];
    int tid = threadIdx.x;
    int m0 = blockIdx.y * 128;
    int n0 = blockIdx.x * 128;
    int lm = tid >> 1;
    int kq = (tid & 1) * 4;
    int tx = tid & 15, ty = tid >> 4;

    const float* Ap = A + (size_t)(m0 + lm) * HH + kq;
    const float* Bp = B + (size_t)(n0 + lm) * HH + kq;

    float4 ra = *(const float4*)Ap;
    float4 rb = *(const float4*)Bp;
    As[0][kq + 0][lm] = ra.x; As[0][kq + 1][lm] = ra.y;
    As[0][kq + 2][lm] = ra.z; As[0][kq + 3][lm] = ra.w;
    Bs[0][kq + 0][lm] = rb.x; Bs[0][kq + 1][lm] = rb.y;
    Bs[0][kq + 2][lm] = rb.z; Bs[0][kq + 3][lm] = rb.w;
    __syncthreads();

    unsigned long long accp[8][4];
    #pragma unroll
    for (int i = 0; i < 8; ++i)
        #pragma unroll
        for (int j = 0; j < 4; ++j) accp[i][j] = 0ull;

    const int nk = HH / 8;
    for (int kt = 0; kt < nk; ++kt) {
        int buf = kt & 1;
        if (kt + 1 < nk) {
            ra = *(const float4*)(Ap + (kt + 1) * 8);
            rb = *(const float4*)(Bp + (kt + 1) * 8);
        }
        #pragma unroll
        for (int kk = 0; kk < 8; ++kk) {
            float a[8];
            *(float4*)&a[0] = *(const float4*)&As[buf][kk][ty * 8];
            *(float4*)&a[4] = *(const float4*)&As[buf][kk][ty * 8 + 4];
            unsigned long long bbv[4];
            {
                ulonglong2 b0 = *(const ulonglong2*)&Bs[buf][kk][tx * 8];
                ulonglong2 b1 = *(const ulonglong2*)&Bs[buf][kk][tx * 8 + 4];
                bbv[0] = b0.x; bbv[1] = b0.y; bbv[2] = b1.x; bbv[3] = b1.y;
            }
            #pragma unroll
            for (int i = 0; i < 8; ++i) {
                unsigned long long aa;
                asm("mov.b64 %0, {%1, %1};" : "=l"(aa) : "f"(a[i]));
                #pragma unroll
                for (int j = 0; j < 4; ++j)
                    asm("fma.rn.f32x2 %0, %1, %2, %0;"
                        : "+l"(accp[i][j]) : "l"(aa), "l"(bbv[j]));
            }
        }
        __syncthreads();
        if (kt + 1 < nk) {
            int nb = buf ^ 1;
            As[nb][kq + 0][lm] = ra.x; As[nb][kq + 1][lm] = ra.y;
            As[nb][kq + 2][lm] = ra.z; As[nb][kq + 3][lm] = ra.w;
            Bs[nb][kq + 0][lm] = rb.x; Bs[nb][kq + 1][lm] = rb.y;
            Bs[nb][kq + 2][lm] = rb.z; Bs[nb][kq + 3][lm] = rb.w;
            __syncthreads();
        }
    }

    float bias[8];
    #pragma unroll
    for (int j = 0; j < 8; ++j) {
        int n = n0 + tx * 8 + j;
        bias[j] = __ldg(&b1a[n]) + __ldg(&b1b[n]);
    }
    #pragma unroll
    for (int i = 0; i < 8; ++i) {
        int m = m0 + ty * 8 + i;
        float o[8];
        #pragma unroll
        for (int j = 0; j < 4; ++j) {
            float lo, hi;
            asm("mov.b64 {%0, %1}, %2;" : "=f"(lo), "=f"(hi) : "l"(accp[i][j]));
            o[2 * j]     = lo + bias[2 * j];
            o[2 * j + 1] = hi + bias[2 * j + 1];
        }
        *(float4*)&g_pre1[(size_t)m * G4 + n0 + tx * 8]     = *(float4*)&o[0];
        *(float4*)&g_pre1[(size_t)m * G4 + n0 + tx * 8 + 4] = *(float4*)&o[4];
    }
}

// ---------------- y = H1 @ W_out^T + b_out, reorder to (S, steps, O) --------
__global__ __launch_bounds__(256) void k_out(const float* __restrict__ Wout,
                                             const float* __restrict__ bout,
                                             float* __restrict__ out) {
    __shared__ float hs[HH];
    int t = blockIdx.x;
    int tid = threadIdx.x;
    #pragma unroll
    for (int i = 0; i < 4; ++i)
        hs[tid + i * 256] = g_H1[(size_t)t * HH + tid + i * 256];
    __syncthreads();

    int w = tid >> 5, l = tid & 31;
    int s = t & 31, st = t >> 5;
    float* orow = out + ((size_t)s * 128 + st) * 64;
    #pragma unroll
    for (int oi = 0; oi < 8; ++oi) {
        int o = w * 8 + oi;
        const float* wr = Wout + (size_t)o * HH;
        float acc = 0.f;
        #pragma unroll
        for (int j = 0; j < 32; ++j)
            acc = fmaf(__ldg(&wr[l + 32 * j]), hs[l + 32 * j], acc);
        acc += __shfl_xor_sync(0xffffffffu, acc, 16);
        acc += __shfl_xor_sync(0xffffffffu, acc, 8);
        acc += __shfl_xor_sync(0xffffffffu, acc, 4);
        acc += __shfl_xor_sync(0xffffffffu, acc, 2);
        acc += __shfl_xor_sync(0xffffffffu, acc, 1);
        if (l == 0) orow[o] = acc + __ldg(&bout[o]);
    }
}

// ---------------- launch ----------------------------------------------------
extern "C" void kernel_launch(void* const* d_in, const int* in_sizes, int n_in,
                              void* d_out, int out_size) {
    const float* inp   = (const float*)d_in[0];
    const float* W_in  = (const float*)d_in[1];
    const float* b_in  = (const float*)d_in[2];
    const float* W_ih0 = (const float*)d_in[3];
    const float* W_hh0 = (const float*)d_in[4];
    const float* b_ih0 = (const float*)d_in[5];
    const float* b_hh0 = (const float*)d_in[6];
    const float* W_ih1 = (const float*)d_in[7];
    const float* W_hh1 = (const float*)d_in[8];
    const float* b_ih1 = (const float*)d_in[9];
    const float* b_hh1 = (const float*)d_in[10];
    const float* W_out = (const float*)d_in[11];
    const float* b_out = (const float*)d_in[12];
    float* out = (float*)d_out;

    float *pre0, *pre1, *H0, *H1, *hbA, *hbB;
    int *tgA, *tgB;
    cudaGetSymbolAddress((void**)&pre0, g_pre0);
    cudaGetSymbolAddress((void**)&pre1, g_pre1);
    cudaGetSymbolAddress((void**)&H0, g_H0);
    cudaGetSymbolAddress((void**)&H1, g_H1);
    cudaGetSymbolAddress((void**)&hbA, g_hbA);
    cudaGetSymbolAddress((void**)&hbB, g_hbB);
    cudaGetSymbolAddress((void**)&tgA, g_tgA);
    cudaGetSymbolAddress((void**)&tgB, g_tgB);

    k_init<<<1, 1024>>>();                                   // 0
    k_wc0<<<G4 / 4, 256>>>(W_ih0, W_in);                     // 1
    k_bc0<<<G4 / 256, 256>>>(W_ih0, b_in, b_ih0, b_hh0);     // 2
    k_pre0<<<dim3(64, 64), 256>>>(inp);                      // 3

    k_chain<<<NCTA, 1024>>>(W_hh0, pre0, H0, hbA, tgA);      // 4  <- ncu slot

    k_pre1<<<dim3(32, 32), 256>>>(H0, W_ih1, b_ih1, b_hh1);  // 5
    k_chain<<<NCTA, 1024>>>(W_hh1, pre1, H1, hbB, tgB);      // 6
    k_out<<<T_STEPS, 256>>>(W_out, b_out, out);              // 7
}

// round 5
// speedup vs baseline: 6.4475x; 6.4475x over previous
#include <cuda_runtime.h>
#include <cstdint>
#include <cmath>

#define T_STEPS 4096
#define HH      1024
#define G4      4096          // 4*H gate rows
#define NCTA    128
#define UPC     8             // hidden units per CTA (1024/128)
#define IND     64
#define OUTD    64
#define PACCW   136           // padded pacc row stride — bank-conflict-free

// ---------------- scratch (static __device__ — no allocation allowed) -------
__device__ float g_Wc0[G4 * IND];              // W_ih0 @ W_in   (4096 x 64)
__device__ float g_bc0[G4];                    // W_ih0@b_in + b_ih0 + b_hh0
__device__ float g_pre0[(size_t)T_STEPS * G4]; // 64 MB
__device__ float g_pre1[(size_t)T_STEPS * G4]; // 64 MB
__device__ float g_H0[(size_t)T_STEPS * HH];   // 16 MB
__device__ float g_H1[(size_t)T_STEPS * HH];   // 16 MB
__device__ unsigned int g_ctr2[2];

// ---------------- counter reset ---------------------------------------------
__global__ void k_init() { g_ctr2[0] = 0u; g_ctr2[1] = 0u; }

// ---------------- merged: Wc0 = W_ih0 @ W_in  AND  bc0 ----------------------
// blocks [0, 1024): Wc0 rows (4 per block). blocks [1024, 1040): bc0.
__global__ __launch_bounds__(256) void k_wcbc(const float* __restrict__ Wih0,
                                              const float* __restrict__ Win,
                                              const float* __restrict__ b_in,
                                              const float* __restrict__ b_ih0,
                                              const float* __restrict__ b_hh0) {
    int tid = threadIdx.x;
    if (blockIdx.x < G4 / 4) {
        int tx = tid & 63;
        int ty = tid >> 6;
        int r = blockIdx.x * 4 + ty;
        const float* wr = Wih0 + (size_t)r * HH;
        float acc = 0.f;
        for (int k = 0; k < HH; ++k)
            acc = fmaf(__ldg(&wr[k]), __ldg(&Win[k * IND + tx]), acc);
        g_Wc0[r * IND + tx] = acc;
    } else {
        int r = (blockIdx.x - G4 / 4) * 256 + tid;
        const float* wr = Wih0 + (size_t)r * HH;
        float acc = 0.f;
        for (int k = 0; k < HH; ++k)
            acc = fmaf(wr[k], __ldg(&b_in[k]), acc);
        g_bc0[r] = acc + b_ih0[r] + b_hh0[r];
    }
}

// ---------------- pre0 = x @ Wc0^T + bc0   (M=4096, N=4096, K=64) -----------
__global__ __launch_bounds__(256) void k_pre0(const float* __restrict__ inp) {
    __shared__ float Xs[64][IND];
    __shared__ float Ws[64][IND];
    int tid = threadIdx.x;
    int t0 = blockIdx.y * 64;
    int r0 = blockIdx.x * 64;

    #pragma unroll
    for (int i = 0; i < 16; ++i) {
        int idx = tid + i * 256;
        int tr = idx >> 6, d = idx & 63;
        int t = t0 + tr;
        int s = t & 31, st = t >> 5;
        Xs[tr][d] = inp[((size_t)s * 128 + st) * 64 + d];
        Ws[tr][d] = g_Wc0[(r0 + tr) * IND + d];
    }
    __syncthreads();

    int tx = tid & 15, ty = tid >> 4;
    float acc[4][4] = {};
    for (int d = 0; d < 64; ++d) {
        float a[4], b[4];
        #pragma unroll
        for (int i = 0; i < 4; ++i) a[i] = Xs[ty * 4 + i][d];
        #pragma unroll
        for (int j = 0; j < 4; ++j) b[j] = Ws[tx * 4 + j][d];
        #pragma unroll
        for (int i = 0; i < 4; ++i)
            #pragma unroll
            for (int j = 0; j < 4; ++j)
                acc[i][j] = fmaf(a[i], b[j], acc[i][j]);
    }
    #pragma unroll
    for (int i = 0; i < 4; ++i) {
        int t = t0 + ty * 4 + i;
        #pragma unroll
        for (int j = 0; j < 4; ++j) {
            int r = r0 + tx * 4 + j;
            g_pre0[(size_t)t * G4 + r] = acc[i][j] + g_bc0[r];
        }
    }
}

// ---------------- fast activations ------------------------------------------
__device__ __forceinline__ float sigf(float x) {
    return __fdividef(1.f, 1.f + __expf(-x));
}
__device__ __forceinline__ float tanh_fast(float x) {
    float e = __expf(2.f * x);
    return 1.f - __fdividef(2.f, e + 1.f);
}

// ---------------- persistent LSTM chain -------------------------------------
// 128 CTAs x 1024 threads, grid-resident (1 CTA/SM).
// Matvec: warp w: unit ul=w>>2, quarter q=w&3; lane l covers k=[q*256+l*8,+8)
//   for all 4 gates of unit ul; h slice loaded DIRECTLY from Hout[t-1] (L1).
// Reduce+cell: warp u<8 owns unit u (lane = gate g=l>>3, seg j=l&7).
// Sync: named bar over warps 0..7, tid0 release-red + acquire-poll on counter,
// then one full __syncthreads. Two full barriers + one 256-wide per step.
__global__ __launch_bounds__(1024, 1) void k_chain(const float* __restrict__ Whh,
                                                   const float* __restrict__ pre,
                                                   float* __restrict__ Hout,
                                                   int ctr_idx) {
    int tid = threadIdx.x;
    int w = tid >> 5, l = tid & 31;
    int b = blockIdx.x;
    int ubase = b * UPC;
    int ul = w >> 2;          // local unit 0..7
    int q  = w & 3;           // k-quarter 0..3
    int unit = ubase + ul;
    int koff = q * 256 + l * 8;

    __shared__ float pacc[32 * PACCW];

    // resident packed weights: gate g, k = koff + 2j{,+1}
    unsigned long long wp[4][4];
    #pragma unroll
    for (int g = 0; g < 4; ++g) {
        const float* wr = Whh + (size_t)(g * HH + unit) * HH + koff;
        ulonglong2 v0 = *reinterpret_cast<const ulonglong2*>(wr);
        ulonglong2 v1 = *reinterpret_cast<const ulonglong2*>(wr + 4);
        wp[g][0] = v0.x; wp[g][1] = v0.y; wp[g][2] = v1.x; wp[g][3] = v1.y;
    }

    // reduce/cell role constants (warps 0..7)
    int rg = l >> 3;                 // gate 0..3
    int rj = l & 7;                  // segment 0..7
    int grow = rg * HH + ubase + w;  // gate row for reduce warp w
    float preg = 0.f;
    if (w < UPC && rj == 0) preg = __ldg(&pre[grow]);   // pre[t=0]
    float c = 0.f;                   // cell state: warp u lane 0

    unsigned int* ctr = &g_ctr2[ctr_idx];
    __syncthreads();

    for (int t = 0; t < T_STEPS; ++t) {
        // --- load h(t-1) slice straight from global (L1-cached, 8x reuse) ---
        float4 h0, h1;
        if (t == 0) {
            h0 = make_float4(0.f, 0.f, 0.f, 0.f);
            h1 = h0;
        } else {
            const float4* hp = reinterpret_cast<const float4*>(
                Hout + (size_t)(t - 1) * HH + koff);
            h0 = __ldg(hp);
            h1 = __ldg(hp + 1);
        }
        unsigned long long hu0, hu1, hu2, hu3;
        asm("mov.b64 %0, {%1, %2};" : "=l"(hu0) : "f"(h0.x), "f"(h0.y));
        asm("mov.b64 %0, {%1, %2};" : "=l"(hu1) : "f"(h0.z), "f"(h0.w));
        asm("mov.b64 %0, {%1, %2};" : "=l"(hu2) : "f"(h1.x), "f"(h1.y));
        asm("mov.b64 %0, {%1, %2};" : "=l"(hu3) : "f"(h1.z), "f"(h1.w));

        unsigned long long acc[4] = {0ull, 0ull, 0ull, 0ull};
        #pragma unroll
        for (int g = 0; g < 4; ++g) {
            asm("fma.rn.f32x2 %0, %1, %2, %0;" : "+l"(acc[g]) : "l"(wp[g][0]), "l"(hu0));
            asm("fma.rn.f32x2 %0, %1, %2, %0;" : "+l"(acc[g]) : "l"(wp[g][1]), "l"(hu1));
            asm("fma.rn.f32x2 %0, %1, %2, %0;" : "+l"(acc[g]) : "l"(wp[g][2]), "l"(hu2));
            asm("fma.rn.f32x2 %0, %1, %2, %0;" : "+l"(acc[g]) : "l"(wp[g][3]), "l"(hu3));
        }
        #pragma unroll
        for (int g = 0; g < 4; ++g) {
            float lo, hi;
            asm("mov.b64 {%0, %1}, %2;" : "=f"(lo), "=f"(hi) : "l"(acc[g]));
            pacc[(ul * 4 + g) * PACCW + q * 32 + l] = lo + hi;
        }
        __syncthreads();                                 // BAR1: pacc ready

        // --- fused reduce + cell: warps 0..7 only ---------------------------
        if (w < UPC) {
            int prow = (w * 4 + rg) * PACCW;
            float s = 0.f;
            #pragma unroll
            for (int i = 0; i < 16; ++i)
                s += pacc[prow + 8 * i + rj];
            s += __shfl_xor_sync(0xffffffffu, s, 4);
            s += __shfl_xor_sync(0xffffffffu, s, 2);
            s += __shfl_xor_sync(0xffffffffu, s, 1);
            if (rj == 0) {
                s += preg;
                if (t + 1 < T_STEPS)                      // prefetch pre[t+1]
                    preg = __ldcg(&pre[(size_t)(t + 1) * G4 + grow]);
            }
            float gi = __shfl_sync(0xffffffffu, s, 0);
            float gf = __shfl_sync(0xffffffffu, s, 8);
            float gg = __shfl_sync(0xffffffffu, s, 16);
            float go = __shfl_sync(0xffffffffu, s, 24);
            if (l == 0) {
                float cn = sigf(gf) * c + sigf(gi) * tanh_fast(gg);
                c = cn;
                float h = sigf(go) * tanh_fast(cn);
                __stcg(&Hout[(size_t)t * HH + ubase + w], h);
            }
            // named barrier over warps 0..7 (256 threads) — h stores visible
            asm volatile("bar.sync 1, 256;" ::: "memory");
            if (tid == 0) {
                __threadfence();
                asm volatile("red.release.gpu.global.add.u32 [%0], 1;"
                             :: "l"(ctr) : "memory");
                unsigned int v, target = (unsigned int)(t + 1) * (unsigned int)NCTA;
                do {
                    asm volatile("ld.acquire.gpu.global.u32 %0, [%1];"
                                 : "=r"(v) : "l"(ctr) : "memory");
                } while (v < target);
            }
        }
        __syncthreads();                                 // BAR2: step globally done
    }
}

// ---------------- pre1 = H0 @ W_ih1^T + (b_ih1 + b_hh1) ---------------------
__global__ __launch_bounds__(256) void k_pre1(const float* __restrict__ A,
                                              const float* __restrict__ B,
                                              const float* __restrict__ b1a,
                                              const float* __restrict__ b1b) {
    __shared__ float As[2][8][132];
    __shared__ float Bs[2][8][132];
    int tid = threadIdx.x;
    int m0 = blockIdx.y * 128;
    int n0 = blockIdx.x * 128;
    int lm = tid >> 1;
    int kq = (tid & 1) * 4;
    int tx = tid & 15, ty = tid >> 4;

    const float* Ap = A + (size_t)(m0 + lm) * HH + kq;
    const float* Bp = B + (size_t)(n0 + lm) * HH + kq;

    float4 ra = *(const float4*)Ap;
    float4 rb = *(const float4*)Bp;
    As[0][kq + 0][lm] = ra.x; As[0][kq + 1][lm] = ra.y;
    As[0][kq + 2][lm] = ra.z; As[0][kq + 3][lm] = ra.w;
    Bs[0][kq + 0][lm] = rb.x; Bs[0][kq + 1][lm] = rb.y;
    Bs[0][kq + 2][lm] = rb.z; Bs[0][kq + 3][lm] = rb.w;
    __syncthreads();

    unsigned long long accp[8][4];
    #pragma unroll
    for (int i = 0; i < 8; ++i)
        #pragma unroll
        for (int j = 0; j < 4; ++j) accp[i][j] = 0ull;

    const int nk = HH / 8;
    for (int kt = 0; kt < nk; ++kt) {
        int buf = kt & 1;
        if (kt + 1 < nk) {
            ra = *(const float4*)(Ap + (kt + 1) * 8);
            rb = *(const float4*)(Bp + (kt + 1) * 8);
        }
        #pragma unroll
        for (int kk = 0; kk < 8; ++kk) {
            float a[8];
            *(float4*)&a[0] = *(const float4*)&As[buf][kk][ty * 8];
            *(float4*)&a[4] = *(const float4*)&As[buf][kk][ty * 8 + 4];
            unsigned long long bbv[4];
            {
                ulonglong2 b0 = *(const ulonglong2*)&Bs[buf][kk][tx * 8];
                ulonglong2 b1 = *(const ulonglong2*)&Bs[buf][kk][tx * 8 + 4];
                bbv[0] = b0.x; bbv[1] = b0.y; bbv[2] = b1.x; bbv[3] = b1.y;
            }
            #pragma unroll
            for (int i = 0; i < 8; ++i) {
                unsigned long long aa;
                asm("mov.b64 %0, {%1, %1};" : "=l"(aa) : "f"(a[i]));
                #pragma unroll
                for (int j = 0; j < 4; ++j)
                    asm("fma.rn.f32x2 %0, %1, %2, %0;"
                        : "+l"(accp[i][j]) : "l"(aa), "l"(bbv[j]));
            }
        }
        __syncthreads();
        if (kt + 1 < nk) {
            int nb = buf ^ 1;
            As[nb][kq + 0][lm] = ra.x; As[nb][kq + 1][lm] = ra.y;
            As[nb][kq + 2][lm] = ra.z; As[nb][kq + 3][lm] = ra.w;
            Bs[nb][kq + 0][lm] = rb.x; Bs[nb][kq + 1][lm] = rb.y;
            Bs[nb][kq + 2][lm] = rb.z; Bs[nb][kq + 3][lm] = rb.w;
            __syncthreads();
        }
    }

    float bias[8];
    #pragma unroll
    for (int j = 0; j < 8; ++j) {
        int n = n0 + tx * 8 + j;
        bias[j] = __ldg(&b1a[n]) + __ldg(&b1b[n]);
    }
    #pragma unroll
    for (int i = 0; i < 8; ++i) {
        int m = m0 + ty * 8 + i;
        float o[8];
        #pragma unroll
        for (int j = 0; j < 4; ++j) {
            float lo, hi;
            asm("mov.b64 {%0, %1}, %2;" : "=f"(lo), "=f"(hi) : "l"(accp[i][j]));
            o[2 * j]     = lo + bias[2 * j];
            o[2 * j + 1] = hi + bias[2 * j + 1];
        }
        *(float4*)&g_pre1[(size_t)m * G4 + n0 + tx * 8]     = *(float4*)&o[0];
        *(float4*)&g_pre1[(size_t)m * G4 + n0 + tx * 8 + 4] = *(float4*)&o[4];
    }
}

// ---------------- y = H1 @ W_out^T + b_out, reorder to (S, steps, O) --------
__global__ __launch_bounds__(256) void k_out(const float* __restrict__ Wout,
                                             const float* __restrict__ bout,
                                             float* __restrict__ out) {
    __shared__ float hs[HH];
    int t = blockIdx.x;
    int tid = threadIdx.x;
    #pragma unroll
    for (int i = 0; i < 4; ++i)
        hs[tid + i * 256] = g_H1[(size_t)t * HH + tid + i * 256];
    __syncthreads();

    int w = tid >> 5, l = tid & 31;
    int s = t & 31, st = t >> 5;
    float* orow = out + ((size_t)s * 128 + st) * 64;
    #pragma unroll
    for (int oi = 0; oi < 8; ++oi) {
        int o = w * 8 + oi;
        const float* wr = Wout + (size_t)o * HH;
        float acc = 0.f;
        #pragma unroll
        for (int j = 0; j < 32; ++j)
            acc = fmaf(__ldg(&wr[l + 32 * j]), hs[l + 32 * j], acc);
        acc += __shfl_xor_sync(0xffffffffu, acc, 16);
        acc += __shfl_xor_sync(0xffffffffu, acc, 8);
        acc += __shfl_xor_sync(0xffffffffu, acc, 4);
        acc += __shfl_xor_sync(0xffffffffu, acc, 2);
        acc += __shfl_xor_sync(0xffffffffu, acc, 1);
        if (l == 0) orow[o] = acc + __ldg(&bout[o]);
    }
}

// ---------------- launch ----------------------------------------------------
// chain0 at launch index 3 (ncu capture offset observed = -2 from -s 5).
extern "C" void kernel_launch(void* const* d_in, const int* in_sizes, int n_in,
                              void* d_out, int out_size) {
    const float* inp   = (const float*)d_in[0];
    const float* W_in  = (const float*)d_in[1];
    const float* b_in  = (const float*)d_in[2];
    const float* W_ih0 = (const float*)d_in[3];
    const float* W_hh0 = (const float*)d_in[4];
    const float* b_ih0 = (const float*)d_in[5];
    const float* b_hh0 = (const float*)d_in[6];
    const float* W_ih1 = (const float*)d_in[7];
    const float* W_hh1 = (const float*)d_in[8];
    const float* b_ih1 = (const float*)d_in[9];
    const float* b_hh1 = (const float*)d_in[10];
    const float* W_out = (const float*)d_in[11];
    const float* b_out = (const float*)d_in[12];
    float* out = (float*)d_out;

    float *pre0, *pre1, *H0, *H1;
    cudaGetSymbolAddress((void**)&pre0, g_pre0);
    cudaGetSymbolAddress((void**)&pre1, g_pre1);
    cudaGetSymbolAddress((void**)&H0, g_H0);
    cudaGetSymbolAddress((void**)&H1, g_H1);

    k_init<<<1, 1>>>();                                             // 0
    k_wcbc<<<G4 / 4 + 16, 256>>>(W_ih0, W_in, b_in, b_ih0, b_hh0);  // 1
    k_pre0<<<dim3(64, 64), 256>>>(inp);                             // 2

    k_chain<<<NCTA, 1024>>>(W_hh0, pre0, H0, 0);                    // 3 <- ncu

    k_pre1<<<dim3(32, 32), 256>>>(H0, W_ih1, b_ih1, b_hh1);         // 4
    k_chain<<<NCTA, 1024>>>(W_hh1, pre1, H1, 1);                    // 5
    k_out<<<T_STEPS, 256>>>(W_out, b_out, out);                     // 6
}